// round 12
// baseline (speedup 1.0000x reference)
#include <cuda_runtime.h>
#include <cuda_bf16.h>
#include <cstdint>
#include <math.h>

#define BATCH 8
#define TQ    2048
#define TK    2048
#define HD    1024

#if defined(__CUDA_ARCH_FEAT_SM103_ALL) || defined(__CUDA_ARCH_FEAT_SM100_ALL)
#define HAS_TCGEN05 1
#else
#define HAS_TCGEN05 0
#endif

// ---------------------------------------------------------------------------
// Device scratch. GEMM operands stored TILED: contiguous 16KB blocks that are
// the exact SW128 smem image of a 128-row x 64-col bf16 sub-tile.
//   Q  : [B][TQ/128=16][HD/64=16] blocks
//   K  : [B][TK/128=16][HD/64=16] blocks
//   KT : [B][HD/128= 8][TK/64=32] blocks
//   P  : [B][TQ/128=16][TK/64=32] blocks
// ---------------------------------------------------------------------------
__device__ float         g_E   [(size_t)BATCH * TQ * TK];
__device__ __nv_bfloat16 g_Qhi [(size_t)BATCH * TQ * HD];
__device__ __nv_bfloat16 g_Qlo [(size_t)BATCH * TQ * HD];
__device__ __nv_bfloat16 g_Khi [(size_t)BATCH * TK * HD];
__device__ __nv_bfloat16 g_Klo [(size_t)BATCH * TK * HD];
__device__ __nv_bfloat16 g_KThi[(size_t)BATCH * HD * TK];
__device__ __nv_bfloat16 g_KTlo[(size_t)BATCH * HD * TK];
__device__ __nv_bfloat16 g_Phi [(size_t)BATCH * TQ * TK];
__device__ __nv_bfloat16 g_Plo [(size_t)BATCH * TQ * TK];

// ---------------------------------------------------------------------------
// Common helpers
// ---------------------------------------------------------------------------
__device__ __forceinline__ uint32_t smem_u32(const void* p) {
    uint32_t a;
    asm("{ .reg .u64 t; cvta.to.shared.u64 t, %1; cvt.u32.u64 %0, t; }" : "=r"(a) : "l"(p));
    return a;
}

__device__ __forceinline__ void split_bf16(float x, __nv_bfloat16& h, __nv_bfloat16& l) {
    h = __float2bfloat16(x);
    l = __float2bfloat16(x - __bfloat162float(h));
}

__device__ __forceinline__ uint32_t pack2(__nv_bfloat16 a, __nv_bfloat16 b) {
    __nv_bfloat162 t(a, b);
    return *(uint32_t*)&t;
}

__device__ __forceinline__ uint32_t sw128(uint32_t off) {
    return off ^ ((off >> 3) & 0x70);
}

#define CP_ASYNC16(dst, src) \
    asm volatile("cp.async.cg.shared.global [%0], [%1], 16;" :: "r"(dst), "l"(src) : "memory")
#define CP_COMMIT()  asm volatile("cp.async.commit_group;" ::: "memory")
#define CP_WAITG(n)  asm volatile("cp.async.wait_group %0;" :: "n"(n) : "memory")

#define CLUSTER_ARRIVE() asm volatile("barrier.cluster.arrive.aligned;" ::: "memory")
#define CLUSTER_WAIT()   asm volatile("barrier.cluster.wait.aligned;"   ::: "memory")

// ---------------------------------------------------------------------------
// tcgen05 helpers (only in the sm_103a feature pass)
// ---------------------------------------------------------------------------
#if HAS_TCGEN05
__device__ __forceinline__ uint32_t elect_one() {
    uint32_t p;
    asm volatile("{\n\t.reg .pred p;\n\telect.sync _|p, 0xFFFFFFFF;\n\tselp.b32 %0, 1, 0, p;\n\t}"
                 : "=r"(p));
    return p;
}

#define MBARRIER_INIT(addr, cnt) \
    asm volatile("mbarrier.init.shared.b64 [%0], %1;" :: "r"((uint32_t)(addr)), "r"((uint32_t)(cnt)) : "memory")

#define MBARRIER_WAIT_PARITY(addr, parity) do {                                              \
    uint32_t _m = (uint32_t)(addr); uint32_t _p = (uint32_t)(parity); uint32_t _d;            \
    asm volatile("{\n\t.reg .pred p;\n\t"                                                     \
        "mbarrier.try_wait.parity.acquire.cta.shared::cta.b64 p, [%1], %2;\n\t"               \
        "selp.b32 %0, 1, 0, p;\n\t}" : "=r"(_d) : "r"(_m), "r"(_p) : "memory");               \
    if (!_d) {                                                                                \
        asm volatile("{\n\t.reg .pred P1;\n\t"                                                \
            "WL_%=:\n\t"                                                                      \
            "mbarrier.try_wait.parity.acquire.cta.shared::cta.b64 P1, [%0], %1, 0x989680;\n\t"\
            "@P1 bra.uni WD_%=;\n\t"                                                          \
            "bra.uni WL_%=;\n\t"                                                              \
            "WD_%=:\n\t}" :: "r"(_m), "r"(_p) : "memory");                                    \
    }                                                                                         \
} while (0)

// arrive on the same-offset mbarrier in cluster CTA `rank` (R8-proven)
#define MBARRIER_ARRIVE_CLUSTER(local_addr, rank) \
    asm volatile("{\n\t.reg .b32 r;\n\t" \
        "mapa.shared::cluster.u32 r, %0, %1;\n\t" \
        "mbarrier.arrive.release.cluster.shared::cluster.b64 _, [r];\n\t}" \
        :: "r"((uint32_t)(local_addr)), "r"((uint32_t)(rank)) : "memory")

#define TCGEN05_ALLOC_CG2(smem_addr, ncols) \
    asm volatile("tcgen05.alloc.cta_group::2.sync.aligned.shared::cta.b32 [%0], %1;" \
                 :: "r"((uint32_t)(smem_addr)), "r"((uint32_t)(ncols)) : "memory")
#define TCGEN05_DEALLOC_CG2(tmem, ncols) \
    asm volatile("tcgen05.dealloc.cta_group::2.sync.aligned.b32 %0, %1;" :: "r"(tmem), "r"((uint32_t)(ncols)))
#define TCGEN05_RELINQUISH_CG2() \
    asm volatile("tcgen05.relinquish_alloc_permit.cta_group::2.sync.aligned;")
#define TCGEN05_COMMIT_MC_CG2(mbar) \
    asm volatile("tcgen05.commit.cta_group::2.mbarrier::arrive::one.shared::cluster.multicast::cluster.b64 [%0], %1;" \
                 :: "r"((uint32_t)(mbar)), "h"((uint16_t)0x3) : "memory")
#define TCGEN05_FENCE_AFTER()  asm volatile("tcgen05.fence::after_thread_sync;"  ::: "memory")
#define TCGEN05_FENCE_BEFORE() asm volatile("tcgen05.fence::before_thread_sync;" ::: "memory")
#define TCGEN05_WAIT_LD()      asm volatile("tcgen05.wait::ld.sync.aligned;"     ::: "memory")
#define FENCE_PROXY_ASYNC()    asm volatile("fence.proxy.async.shared::cta;"     ::: "memory")

#define TCGEN05_LD_32X32B_X32(r, tmem_addr) \
    asm volatile( \
        "tcgen05.ld.sync.aligned.32x32b.x32.b32 " \
        "{%0, %1, %2, %3, %4, %5, %6, %7, " \
        " %8, %9, %10, %11, %12, %13, %14, %15, " \
        " %16, %17, %18, %19, %20, %21, %22, %23, " \
        " %24, %25, %26, %27, %28, %29, %30, %31}, [%32];" \
        : "=r"((r)[0]),  "=r"((r)[1]),  "=r"((r)[2]),  "=r"((r)[3]), \
          "=r"((r)[4]),  "=r"((r)[5]),  "=r"((r)[6]),  "=r"((r)[7]), \
          "=r"((r)[8]),  "=r"((r)[9]),  "=r"((r)[10]), "=r"((r)[11]), \
          "=r"((r)[12]), "=r"((r)[13]), "=r"((r)[14]), "=r"((r)[15]), \
          "=r"((r)[16]), "=r"((r)[17]), "=r"((r)[18]), "=r"((r)[19]), \
          "=r"((r)[20]), "=r"((r)[21]), "=r"((r)[22]), "=r"((r)[23]), \
          "=r"((r)[24]), "=r"((r)[25]), "=r"((r)[26]), "=r"((r)[27]), \
          "=r"((r)[28]), "=r"((r)[29]), "=r"((r)[30]), "=r"((r)[31]) \
        : "r"(tmem_addr))

__device__ __forceinline__ void mma_f16_ss_cg2(uint32_t d, uint64_t ad, uint64_t bd,
                                               uint32_t idesc, bool acc) {
    uint32_t en = acc ? 1u : 0u;
    asm volatile(
        "{\n\t.reg .pred p;\n\tsetp.ne.u32 p, %5, 0;\n\t"
        "tcgen05.mma.cta_group::2.kind::f16 [%0], %1, %2, %3, "
        "{%4, %4, %4, %4, %4, %4, %4, %4}, p;\n\t}"
        :: "r"(d), "l"(ad), "l"(bd), "r"(idesc), "r"(0u), "r"(en) : "memory");
}

__device__ __forceinline__ uint64_t make_desc(uint32_t addr) {
    const uint64_t base = (2ULL << 61) | (1ULL << 46) | (64ULL << 32) | (1ULL << 16);
    return base | ((uint64_t)(addr >> 4) & 0x3FFF);
}
// dtype=F32, a/b=BF16, N=256 (32<<17), M=256 (16<<24) for cta_group::2
#define MMA_IDESC_CG2 0x10400490u
#endif  // HAS_TCGEN05

// ---------------------------------------------------------------------------
// GEMM: C[M,N] = (Ahi+Alo)[M,Kt] * (Bhi+Blo)[N,Kt]^T, fp32 out, TILED operands.
// 2-CTA cluster: M=256 (128/CTA), N=256 (128/CTA). K chunk 64, 3 smem stages.
// Warp 0 = cp.async producer (2-chunk lookahead); warp 1 rank0 = MMA issuer.
// Cold waiters gate on a ONCE-ONLY FINAL barrier (phase-parity aliasing fix).
// Grid: x = (N/256)*2, y = M/256, z = batch.
// ---------------------------------------------------------------------------
#define NSTAGES     3
#define SM_TMEMPTR  0
#define SM_READY(b) (16 + 8 * (b))
#define SM_DONE(b)  (48 + 8 * (b))
#define SM_FINAL    72
#define SM_BUF      1024
#define STAGE_BYTES 65536          // Ahi | Alo | Bhi | Blo, 16KB each
#define GEMM_SMEM   (SM_BUF + NSTAGES * STAGE_BYTES)

__global__ void __launch_bounds__(256, 1) __cluster_dims__(2, 1, 1)
gemm_split_kernel(const __nv_bfloat16* __restrict__ Ahi, const __nv_bfloat16* __restrict__ Alo,
                  const __nv_bfloat16* __restrict__ Bhi, const __nv_bfloat16* __restrict__ Blo,
                  float* __restrict__ C, int M, int N, int Ktot)
{
#if HAS_TCGEN05
    extern __shared__ char smem[];
    const uint32_t sb = smem_u32(smem);
    const int tid = threadIdx.x;
    const int wid = tid >> 5, lid = tid & 31;
    const int rank = (int)(blockIdx.x & 1);
    const int n0 = (int)(blockIdx.x >> 1) * 256;
    const int m0 = (int)blockIdx.y * 256;

    const int mt128 = M >> 7, nt128 = N >> 7;
    const int nch = Ktot >> 6;
    const int atile = (int)blockIdx.y * 2 + rank;
    const int btile = (int)(blockIdx.x >> 1) * 2 + rank;
    const size_t ablk0 = ((size_t)blockIdx.z * mt128 + atile) * nch;
    const size_t bblk0 = ((size_t)blockIdx.z * nt128 + btile) * nch;
    // byte pointers to this CTA's chunk-0 blocks (16KB per chunk)
    const char* aHiB = (const char*)(Ahi + ablk0 * 8192);
    const char* aLoB = (const char*)(Alo + ablk0 * 8192);
    const char* bHiB = (const char*)(Bhi + bblk0 * 8192);
    const char* bLoB = (const char*)(Blo + bblk0 * 8192);

    if (wid == 0) TCGEN05_ALLOC_CG2(sb + SM_TMEMPTR, 256);
    if (tid == 0) {
#pragma unroll
        for (int b = 0; b < NSTAGES; b++) {
            MBARRIER_INIT(sb + SM_READY(b), 2);   // one arrive per CTA
            MBARRIER_INIT(sb + SM_DONE(b), 1);    // multicast commit per chunk
        }
        MBARRIER_INIT(sb + SM_FINAL, 1);          // completes EXACTLY once
    }
    __syncthreads();
    uint32_t tmem;
    asm volatile("ld.shared.b32 %0, [%1];" : "=r"(tmem) : "r"(sb + SM_TMEMPTR));

    CLUSTER_ARRIVE(); CLUSTER_WAIT();

    if (wid == 0) {
        // ================= producer warp (both ranks) =================
        // All its DONE waits start at phase 0 and proceed sequentially per
        // buffer -> no parity aliasing.
        const char* srcs[4] = { aHiB, aLoB, bHiB, bLoB };
#pragma unroll 1
        for (int c = 0; c < nch; c++) {
            const int buf = c % NSTAGES;
            if (c >= NSTAGES) {
                MBARRIER_WAIT_PARITY(sb + SM_DONE(buf), ((c / NSTAGES) - 1) & 1);
            }
            const uint32_t stage = sb + SM_BUF + buf * STAGE_BYTES;
            const size_t coff = (size_t)c * 16384;
#pragma unroll
            for (int s = 0; s < 4; s++) {
                const char* gs = srcs[s] + coff;
                const uint32_t ds = stage + s * 16384;
#pragma unroll
                for (int it = 0; it < 32; it++) {
                    const uint32_t o = (uint32_t)(it * 32 + lid) * 16;
                    CP_ASYNC16(ds + o, gs + o);
                }
            }
            CP_COMMIT();
            if (c >= 2) {
                CP_WAITG(2);                 // chunk c-2 complete
                __syncwarp();
                FENCE_PROXY_ASYNC();
                if (elect_one())
                    MBARRIER_ARRIVE_CLUSTER(sb + SM_READY((c - 2) % NSTAGES), 0);
            }
        }
        // drain last two chunks
        CP_WAITG(1);
        __syncwarp();
        FENCE_PROXY_ASYNC();
        if (elect_one()) MBARRIER_ARRIVE_CLUSTER(sb + SM_READY((nch - 2) % NSTAGES), 0);
        CP_WAITG(0);
        __syncwarp();
        FENCE_PROXY_ASYNC();
        if (elect_one()) MBARRIER_ARRIVE_CLUSTER(sb + SM_READY((nch - 1) % NSTAGES), 0);
    } else if (wid == 1 && rank == 0 && elect_one()) {
        // ================= MMA issuer (rank 0) =================
        // READY waits are sequential-from-phase-0 -> no aliasing.
#pragma unroll 1
        for (int c = 0; c < nch; c++) {
            const int buf = c % NSTAGES;
            MBARRIER_WAIT_PARITY(sb + SM_READY(buf), (c / NSTAGES) & 1);
            const uint32_t stage = sb + SM_BUF + buf * STAGE_BYTES;
            const uint64_t dAh = make_desc(stage + 0);
            const uint64_t dAl = make_desc(stage + 16384);
            const uint64_t dBh = make_desc(stage + 32768);
            const uint64_t dBl = make_desc(stage + 49152);
            const bool first = (c == 0);
#pragma unroll
            for (int s = 0; s < 4; s++)
                mma_f16_ss_cg2(tmem, dAh + s * 2, dBh + s * 2, MMA_IDESC_CG2, !(first && s == 0));
#pragma unroll
            for (int s = 0; s < 4; s++)
                mma_f16_ss_cg2(tmem, dAh + s * 2, dBl + s * 2, MMA_IDESC_CG2, true);
#pragma unroll
            for (int s = 0; s < 4; s++)
                mma_f16_ss_cg2(tmem, dAl + s * 2, dBh + s * 2, MMA_IDESC_CG2, true);
            TCGEN05_COMMIT_MC_CG2(sb + SM_DONE(buf));
        }
        // once-only terminal commit: arrives on BOTH CTAs' FINAL after ALL
        // MMAs complete. FINAL goes phase 0 -> 1 exactly once, so a cold
        // parity-0 wait below is unambiguous for every thread.
        TCGEN05_COMMIT_MC_CG2(sb + SM_FINAL);
    }

    // ---------------- all threads: once-only final gate, then epilogue ------
    MBARRIER_WAIT_PARITY(sb + SM_FINAL, 0);
    TCGEN05_FENCE_AFTER();

    {
        const int sub = wid & 3, half = wid >> 2;
        const int row = sub * 32 + lid;
        float* crow = C + (size_t)blockIdx.z * M * N
                      + (size_t)(m0 + rank * 128 + row) * N + n0 + half * 128;
#pragma unroll
        for (int g = 0; g < 4; g++) {
            uint32_t regs[32];
            TCGEN05_LD_32X32B_X32(regs, tmem + half * 128 + g * 32);
            TCGEN05_WAIT_LD();
#pragma unroll
            for (int q = 0; q < 8; q++) {
                float4 f;
                f.x = __uint_as_float(regs[q * 4 + 0]);
                f.y = __uint_as_float(regs[q * 4 + 1]);
                f.z = __uint_as_float(regs[q * 4 + 2]);
                f.w = __uint_as_float(regs[q * 4 + 3]);
                *(float4*)(crow + g * 32 + q * 4) = f;
            }
        }
    }
    TCGEN05_FENCE_BEFORE();
    __syncthreads();
    if (wid == 0) {
        TCGEN05_RELINQUISH_CG2();
        TCGEN05_DEALLOC_CG2(tmem, 256);
    }
    CLUSTER_ARRIVE(); CLUSTER_WAIT();
#else
    // =============== non-feature fallback: naive tiled GEMM ===============
    // Never selected on GB300 (feature cubin exists; R6 ncu proved tensor pipe
    // active). Correct-but-slow insurance.
    const int tid = threadIdx.x;
    const int rank = (int)(blockIdx.x & 1);
    const int m0 = (int)blockIdx.y * 256 + rank * 128;
    const int n0 = (int)(blockIdx.x >> 1) * 256;
    const int mt128 = M >> 7, nt128 = N >> 7;
    const int nch = Ktot >> 6;

    auto ld2 = [&](const __nv_bfloat16* hi, const __nv_bfloat16* lo,
                   size_t tblk, int r, int e) -> float {
        const size_t blk = tblk * nch + (e >> 6);
        const uint32_t off = sw128((uint32_t)((r & 127) * 128 + (e & 63) * 2));
        float h = __bfloat162float(*(const __nv_bfloat16*)((const char*)hi + blk * 16384 + off));
        float l = __bfloat162float(*(const __nv_bfloat16*)((const char*)lo + blk * 16384 + off));
        return h + l;
    };

    const size_t atblk = (size_t)blockIdx.z * mt128 + (m0 >> 7);
    for (int idx = tid; idx < 128 * 256; idx += 256) {
        const int r = idx >> 8;
        const int j = idx & 255;
        const int gcol = n0 + j;
        const size_t btblk = (size_t)blockIdx.z * nt128 + (gcol >> 7);
        float acc = 0.0f;
        for (int e = 0; e < Ktot; e++)
            acc += ld2(Ahi, Alo, atblk, r, e) * ld2(Bhi, Blo, btblk, gcol & 127, e);
        C[(size_t)blockIdx.z * M * N + (size_t)(m0 + r) * N + gcol] = acc;
    }
#endif
}

// ---------------------------------------------------------------------------
// Q convert: fp32 row-major -> tiled SW128 bf16 hi/lo blocks.
// ---------------------------------------------------------------------------
__global__ void __launch_bounds__(256)
convert_q_kernel(const float* __restrict__ in,
                 __nv_bfloat16* __restrict__ hi, __nv_bfloat16* __restrict__ lo)
{
    const size_t i = (size_t)blockIdx.x * 256 + threadIdx.x;
    const size_t e0 = i * 8;
    const int b = (int)(e0 >> 21);              // TQ*HD = 2^21
    const int rem = (int)(e0 & ((1u << 21) - 1));
    const int q = rem >> 10;                     // HD = 1024
    const int d = rem & 1023;

    float4 v0 = *(const float4*)(in + e0);
    float4 v1 = *(const float4*)(in + e0 + 4);
    float v[8] = { v0.x, v0.y, v0.z, v0.w, v1.x, v1.y, v1.z, v1.w };
    __nv_bfloat16 h[8], l[8];
#pragma unroll
    for (int j = 0; j < 8; j++) split_bf16(v[j], h[j], l[j]);

    const size_t blk = ((size_t)b * 16 + (q >> 7)) * 16 + (d >> 6);
    const uint32_t off = sw128((uint32_t)((q & 127) * 128 + ((d & 63) >> 3) * 16));
    uint4 hv = { pack2(h[0], h[1]), pack2(h[2], h[3]), pack2(h[4], h[5]), pack2(h[6], h[7]) };
    uint4 lv = { pack2(l[0], l[1]), pack2(l[2], l[3]), pack2(l[4], l[5]), pack2(l[6], l[7]) };
    *(uint4*)((char*)hi + blk * 16384 + off) = hv;
    *(uint4*)((char*)lo + blk * 16384 + off) = lv;
}

// ---------------------------------------------------------------------------
// K convert: one read of K -> tiled K hi/lo (rows=t) AND tiled KT hi/lo (rows=d)
// ---------------------------------------------------------------------------
__global__ void __launch_bounds__(256)
k_convert_kernel(const float* __restrict__ Kin,
                 __nv_bfloat16* __restrict__ Khi, __nv_bfloat16* __restrict__ Klo,
                 __nv_bfloat16* __restrict__ KThi, __nv_bfloat16* __restrict__ KTlo)
{
    __shared__ float tile[32][33];
    const int b = blockIdx.z;
    const int t0 = blockIdx.x * 32, d0 = blockIdx.y * 32;
    const int tx = threadIdx.x & 31, ty = threadIdx.x >> 5;
    const float* src = Kin + (size_t)b * TK * HD;

#pragma unroll
    for (int r = 0; r < 4; r++) {
        const int t = t0 + ty + 8 * r;
        const int d = d0 + tx;
        const float v = src[(size_t)t * HD + d];
        tile[ty + 8 * r][tx] = v;
        __nv_bfloat16 h, l; split_bf16(v, h, l);
        const size_t blk = ((size_t)b * 16 + (t >> 7)) * 16 + (d >> 6);
        const uint32_t off = sw128((uint32_t)((t & 127) * 128 + (d & 63) * 2));
        *(__nv_bfloat16*)((char*)Khi + blk * 16384 + off) = h;
        *(__nv_bfloat16*)((char*)Klo + blk * 16384 + off) = l;
    }
    __syncthreads();
#pragma unroll
    for (int r = 0; r < 4; r++) {
        const int d = d0 + ty + 8 * r;
        const int t = t0 + tx;
        const float v = tile[tx][ty + 8 * r];
        __nv_bfloat16 h, l; split_bf16(v, h, l);
        const size_t blk = ((size_t)b * 8 + (d >> 7)) * 32 + (t >> 6);
        const uint32_t off = sw128((uint32_t)((d & 127) * 128 + (t & 63) * 2));
        *(__nv_bfloat16*)((char*)KThi + blk * 16384 + off) = h;
        *(__nv_bfloat16*)((char*)KTlo + blk * 16384 + off) = l;
    }
}

// ---------------------------------------------------------------------------
// Row softmax over TK; fp32 in (row-major), bf16 hi/lo out (TILED blocks).
// ---------------------------------------------------------------------------
__global__ void __launch_bounds__(256)
softmax_kernel(const float* __restrict__ E,
               __nv_bfloat16* __restrict__ Phi, __nv_bfloat16* __restrict__ Plo)
{
    const size_t row = blockIdx.x;
    const float* e = E + row * (size_t)TK;
    const int tid = threadIdx.x;
    const int lane = tid & 31, warp = tid >> 5;
    __shared__ float red[32];

    float4 a = *(const float4*)(e + tid * 8);
    float4 c = *(const float4*)(e + tid * 8 + 4);
    float v[8] = { a.x, a.y, a.z, a.w, c.x, c.y, c.z, c.w };

    float m = -INFINITY;
#pragma unroll
    for (int i = 0; i < 8; i++) m = fmaxf(m, v[i]);
#pragma unroll
    for (int o = 16; o > 0; o >>= 1) m = fmaxf(m, __shfl_xor_sync(0xffffffffu, m, o));
    if (lane == 0) red[warp] = m;
    __syncthreads();
    if (warp == 0) {
        float t = red[lane & 7];
#pragma unroll
        for (int o = 4; o > 0; o >>= 1) t = fmaxf(t, __shfl_xor_sync(0xffffffffu, t, o));
        red[lane] = t;
    }
    __syncthreads();
    m = red[0];

    float s = 0.0f;
#pragma unroll
    for (int i = 0; i < 8; i++) { v[i] = __expf(v[i] - m); s += v[i]; }
#pragma unroll
    for (int o = 16; o > 0; o >>= 1) s += __shfl_xor_sync(0xffffffffu, s, o);
    __syncthreads();
    if (lane == 0) red[warp] = s;
    __syncthreads();
    if (warp == 0) {
        float t = red[lane & 7];
#pragma unroll
        for (int o = 4; o > 0; o >>= 1) t += __shfl_xor_sync(0xffffffffu, t, o);
        red[lane] = t;
    }
    __syncthreads();
    const float inv = 1.0f / red[0];

    __nv_bfloat16 h[8], l[8];
#pragma unroll
    for (int i = 0; i < 8; i++) split_bf16(v[i] * inv, h[i], l[i]);

    const int b = (int)(row >> 11);             // TQ = 2048
    const int q = (int)(row & 2047);
    const size_t blk = ((size_t)b * 16 + (q >> 7)) * 32 + (tid >> 3);   // nch=32
    const uint32_t off = sw128((uint32_t)((q & 127) * 128 + (tid & 7) * 16));
    uint4 hv = { pack2(h[0], h[1]), pack2(h[2], h[3]), pack2(h[4], h[5]), pack2(h[6], h[7]) };
    uint4 lv = { pack2(l[0], l[1]), pack2(l[2], l[3]), pack2(l[4], l[5]), pack2(l[6], l[7]) };
    *(uint4*)((char*)Phi + blk * 16384 + off) = hv;
    *(uint4*)((char*)Plo + blk * 16384 + off) = lv;
}

// ---------------------------------------------------------------------------
extern "C" void kernel_launch(void* const* d_in, const int* in_sizes, int n_in,
                              void* d_out, int out_size)
{
    const float* Q  = (const float*)d_in[0];
    const float* Kt = (const float*)d_in[1];
    float* O = (float*)d_out;

    float *E; __nv_bfloat16 *Qhi, *Qlo, *Khi, *Klo, *KThi, *KTlo, *Phi, *Plo;
    cudaGetSymbolAddress((void**)&E,    g_E);
    cudaGetSymbolAddress((void**)&Qhi,  g_Qhi);
    cudaGetSymbolAddress((void**)&Qlo,  g_Qlo);
    cudaGetSymbolAddress((void**)&Khi,  g_Khi);
    cudaGetSymbolAddress((void**)&Klo,  g_Klo);
    cudaGetSymbolAddress((void**)&KThi, g_KThi);
    cudaGetSymbolAddress((void**)&KTlo, g_KTlo);
    cudaGetSymbolAddress((void**)&Phi,  g_Phi);
    cudaGetSymbolAddress((void**)&Plo,  g_Plo);

    cudaFuncSetAttribute(gemm_split_kernel,
                         cudaFuncAttributeMaxDynamicSharedMemorySize, GEMM_SMEM);

    // Q -> tiled hi/lo
    {
        size_t n8 = (size_t)BATCH * TQ * HD / 8;
        convert_q_kernel<<<(unsigned)(n8 / 256), 256>>>(Q, Qhi, Qlo);
    }
    // K -> tiled K hi/lo + tiled KT hi/lo
    {
        dim3 grid(TK / 32, HD / 32, BATCH);
        k_convert_kernel<<<grid, 256>>>(Kt, Khi, Klo, KThi, KTlo);
    }
    // GEMM1: E = Q K^T  (M=TQ, N=TK, Ktot=HD)
    {
        dim3 grid((TK / 256) * 2, TQ / 256, BATCH);
        gemm_split_kernel<<<grid, 256, GEMM_SMEM>>>(Qhi, Qlo, Khi, Klo, E, TQ, TK, HD);
    }
    softmax_kernel<<<BATCH * TQ, 256>>>(E, Phi, Plo);
    // GEMM2: O = P KT^T  (M=TQ, N=HD, Ktot=TK)
    {
        dim3 grid((HD / 256) * 2, TQ / 256, BATCH);
        gemm_split_kernel<<<grid, 256, GEMM_SMEM>>>(Phi, Plo, KThi, KTlo, O, TQ, HD, TK);
    }
    (void)in_sizes; (void)n_in; (void)out_size;
}

// round 13
// speedup vs baseline: 1.0915x; 1.0915x over previous
#include <cuda_runtime.h>
#include <cuda_bf16.h>
#include <cstdint>
#include <math.h>

#define BATCH 8
#define TQ    2048
#define TK    2048
#define HD    1024

#if defined(__CUDA_ARCH_FEAT_SM103_ALL) || defined(__CUDA_ARCH_FEAT_SM100_ALL)
#define HAS_TCGEN05 1
#else
#define HAS_TCGEN05 0
#endif

// ---------------------------------------------------------------------------
// Device scratch. GEMM operands stored TILED: contiguous 16KB blocks that are
// the exact SW128 smem image of a 128-row x 64-col bf16 sub-tile.
//   Q  : [B][TQ/128=16][HD/64=16] blocks
//   K  : [B][TK/128=16][HD/64=16] blocks
//   KT : [B][HD/128= 8][TK/64=32] blocks
//   P  : [B][TQ/128=16][TK/64=32] blocks
// ---------------------------------------------------------------------------
__device__ float         g_E   [(size_t)BATCH * TQ * TK];
__device__ __nv_bfloat16 g_Qhi [(size_t)BATCH * TQ * HD];
__device__ __nv_bfloat16 g_Qlo [(size_t)BATCH * TQ * HD];
__device__ __nv_bfloat16 g_Khi [(size_t)BATCH * TK * HD];
__device__ __nv_bfloat16 g_Klo [(size_t)BATCH * TK * HD];
__device__ __nv_bfloat16 g_KThi[(size_t)BATCH * HD * TK];
__device__ __nv_bfloat16 g_KTlo[(size_t)BATCH * HD * TK];
__device__ __nv_bfloat16 g_Phi [(size_t)BATCH * TQ * TK];
__device__ __nv_bfloat16 g_Plo [(size_t)BATCH * TQ * TK];

// ---------------------------------------------------------------------------
// Common helpers
// ---------------------------------------------------------------------------
__device__ __forceinline__ uint32_t smem_u32(const void* p) {
    uint32_t a;
    asm("{ .reg .u64 t; cvta.to.shared.u64 t, %1; cvt.u32.u64 %0, t; }" : "=r"(a) : "l"(p));
    return a;
}

__device__ __forceinline__ void split_bf16(float x, __nv_bfloat16& h, __nv_bfloat16& l) {
    h = __float2bfloat16(x);
    l = __float2bfloat16(x - __bfloat162float(h));
}

__device__ __forceinline__ uint32_t pack2(__nv_bfloat16 a, __nv_bfloat16 b) {
    __nv_bfloat162 t(a, b);
    return *(uint32_t*)&t;
}

__device__ __forceinline__ uint32_t sw128(uint32_t off) {
    return off ^ ((off >> 3) & 0x70);
}

#define CP_ASYNC16(dst, src) \
    asm volatile("cp.async.cg.shared.global [%0], [%1], 16;" :: "r"(dst), "l"(src) : "memory")
#define CP_COMMIT()  asm volatile("cp.async.commit_group;" ::: "memory")
#define CP_WAITG(n)  asm volatile("cp.async.wait_group %0;" :: "n"(n) : "memory")

#define CLUSTER_ARRIVE() asm volatile("barrier.cluster.arrive.aligned;" ::: "memory")
#define CLUSTER_WAIT()   asm volatile("barrier.cluster.wait.aligned;"   ::: "memory")

// ---------------------------------------------------------------------------
// tcgen05 helpers (only in the sm_103a feature pass)
// ---------------------------------------------------------------------------
#if HAS_TCGEN05
__device__ __forceinline__ uint32_t elect_one() {
    uint32_t p;
    asm volatile("{\n\t.reg .pred p;\n\telect.sync _|p, 0xFFFFFFFF;\n\tselp.b32 %0, 1, 0, p;\n\t}"
                 : "=r"(p));
    return p;
}

#define MBARRIER_INIT(addr, cnt) \
    asm volatile("mbarrier.init.shared.b64 [%0], %1;" :: "r"((uint32_t)(addr)), "r"((uint32_t)(cnt)) : "memory")

#define MBARRIER_WAIT_PARITY(addr, parity) do {                                              \
    uint32_t _m = (uint32_t)(addr); uint32_t _p = (uint32_t)(parity); uint32_t _d;            \
    asm volatile("{\n\t.reg .pred p;\n\t"                                                     \
        "mbarrier.try_wait.parity.acquire.cta.shared::cta.b64 p, [%1], %2;\n\t"               \
        "selp.b32 %0, 1, 0, p;\n\t}" : "=r"(_d) : "r"(_m), "r"(_p) : "memory");               \
    if (!_d) {                                                                                \
        asm volatile("{\n\t.reg .pred P1;\n\t"                                                \
            "WL_%=:\n\t"                                                                      \
            "mbarrier.try_wait.parity.acquire.cta.shared::cta.b64 P1, [%0], %1, 0x989680;\n\t"\
            "@P1 bra.uni WD_%=;\n\t"                                                          \
            "bra.uni WL_%=;\n\t"                                                              \
            "WD_%=:\n\t}" :: "r"(_m), "r"(_p) : "memory");                                    \
    }                                                                                         \
} while (0)

// arrive on the same-offset mbarrier in cluster CTA `rank` (R8-proven)
#define MBARRIER_ARRIVE_CLUSTER(local_addr, rank) \
    asm volatile("{\n\t.reg .b32 r;\n\t" \
        "mapa.shared::cluster.u32 r, %0, %1;\n\t" \
        "mbarrier.arrive.release.cluster.shared::cluster.b64 _, [r];\n\t}" \
        :: "r"((uint32_t)(local_addr)), "r"((uint32_t)(rank)) : "memory")

#define TCGEN05_ALLOC_CG2(smem_addr, ncols) \
    asm volatile("tcgen05.alloc.cta_group::2.sync.aligned.shared::cta.b32 [%0], %1;" \
                 :: "r"((uint32_t)(smem_addr)), "r"((uint32_t)(ncols)) : "memory")
#define TCGEN05_DEALLOC_CG2(tmem, ncols) \
    asm volatile("tcgen05.dealloc.cta_group::2.sync.aligned.b32 %0, %1;" :: "r"(tmem), "r"((uint32_t)(ncols)))
#define TCGEN05_RELINQUISH_CG2() \
    asm volatile("tcgen05.relinquish_alloc_permit.cta_group::2.sync.aligned;")
#define TCGEN05_COMMIT_MC_CG2(mbar) \
    asm volatile("tcgen05.commit.cta_group::2.mbarrier::arrive::one.shared::cluster.multicast::cluster.b64 [%0], %1;" \
                 :: "r"((uint32_t)(mbar)), "h"((uint16_t)0x3) : "memory")
#define TCGEN05_FENCE_AFTER()  asm volatile("tcgen05.fence::after_thread_sync;"  ::: "memory")
#define TCGEN05_FENCE_BEFORE() asm volatile("tcgen05.fence::before_thread_sync;" ::: "memory")
#define TCGEN05_WAIT_LD()      asm volatile("tcgen05.wait::ld.sync.aligned;"     ::: "memory")
#define FENCE_PROXY_ASYNC()    asm volatile("fence.proxy.async.shared::cta;"     ::: "memory")

#define TCGEN05_LD_32X32B_X32(r, tmem_addr) \
    asm volatile( \
        "tcgen05.ld.sync.aligned.32x32b.x32.b32 " \
        "{%0, %1, %2, %3, %4, %5, %6, %7, " \
        " %8, %9, %10, %11, %12, %13, %14, %15, " \
        " %16, %17, %18, %19, %20, %21, %22, %23, " \
        " %24, %25, %26, %27, %28, %29, %30, %31}, [%32];" \
        : "=r"((r)[0]),  "=r"((r)[1]),  "=r"((r)[2]),  "=r"((r)[3]), \
          "=r"((r)[4]),  "=r"((r)[5]),  "=r"((r)[6]),  "=r"((r)[7]), \
          "=r"((r)[8]),  "=r"((r)[9]),  "=r"((r)[10]), "=r"((r)[11]), \
          "=r"((r)[12]), "=r"((r)[13]), "=r"((r)[14]), "=r"((r)[15]), \
          "=r"((r)[16]), "=r"((r)[17]), "=r"((r)[18]), "=r"((r)[19]), \
          "=r"((r)[20]), "=r"((r)[21]), "=r"((r)[22]), "=r"((r)[23]), \
          "=r"((r)[24]), "=r"((r)[25]), "=r"((r)[26]), "=r"((r)[27]), \
          "=r"((r)[28]), "=r"((r)[29]), "=r"((r)[30]), "=r"((r)[31]) \
        : "r"(tmem_addr))

__device__ __forceinline__ void mma_f16_ss_cg2(uint32_t d, uint64_t ad, uint64_t bd,
                                               uint32_t idesc, bool acc) {
    uint32_t en = acc ? 1u : 0u;
    asm volatile(
        "{\n\t.reg .pred p;\n\tsetp.ne.u32 p, %5, 0;\n\t"
        "tcgen05.mma.cta_group::2.kind::f16 [%0], %1, %2, %3, "
        "{%4, %4, %4, %4, %4, %4, %4, %4}, p;\n\t}"
        :: "r"(d), "l"(ad), "l"(bd), "r"(idesc), "r"(0u), "r"(en) : "memory");
}

__device__ __forceinline__ uint64_t make_desc(uint32_t addr) {
    const uint64_t base = (2ULL << 61) | (1ULL << 46) | (64ULL << 32) | (1ULL << 16);
    return base | ((uint64_t)(addr >> 4) & 0x3FFF);
}
// dtype=F32, a/b=BF16, N=256 (32<<17), M=256 (16<<24) for cta_group::2
#define MMA_IDESC_CG2 0x10400490u
#endif  // HAS_TCGEN05

// ---------------------------------------------------------------------------
// GEMM: C[M,N] = (Ahi+Alo)[M,Kt] * (Bhi+Blo)[N,Kt]^T, fp32 out, TILED operands.
// 2-CTA cluster: M=256 (128/CTA), N=256 (128/CTA). K chunk 64, 3 smem stages.
// Warps 0-3 = cp.async producers (one 16KB sub-tile each, 2-chunk lookahead);
// warp 4 rank0 = MMA issuer. Cold waiters gate on once-only FINAL barrier.
// Grid: x = (N/256)*2, y = M/256, z = batch.
// ---------------------------------------------------------------------------
#define NSTAGES     3
#define SM_TMEMPTR  0
#define SM_READY(b) (16 + 8 * (b))
#define SM_DONE(b)  (48 + 8 * (b))
#define SM_FINAL    72
#define SM_BUF      1024
#define STAGE_BYTES 65536          // Ahi | Alo | Bhi | Blo, 16KB each
#define GEMM_SMEM   (SM_BUF + NSTAGES * STAGE_BYTES)

__global__ void __launch_bounds__(256, 1) __cluster_dims__(2, 1, 1)
gemm_split_kernel(const __nv_bfloat16* __restrict__ Ahi, const __nv_bfloat16* __restrict__ Alo,
                  const __nv_bfloat16* __restrict__ Bhi, const __nv_bfloat16* __restrict__ Blo,
                  float* __restrict__ C, int M, int N, int Ktot)
{
#if HAS_TCGEN05
    extern __shared__ char smem[];
    const uint32_t sb = smem_u32(smem);
    const int tid = threadIdx.x;
    const int wid = tid >> 5, lid = tid & 31;
    const int rank = (int)(blockIdx.x & 1);
    const int n0 = (int)(blockIdx.x >> 1) * 256;
    const int m0 = (int)blockIdx.y * 256;

    const int mt128 = M >> 7, nt128 = N >> 7;
    const int nch = Ktot >> 6;
    const int atile = (int)blockIdx.y * 2 + rank;
    const int btile = (int)(blockIdx.x >> 1) * 2 + rank;
    const size_t ablk0 = ((size_t)blockIdx.z * mt128 + atile) * nch;
    const size_t bblk0 = ((size_t)blockIdx.z * nt128 + btile) * nch;
    // byte pointers to this CTA's chunk-0 blocks (16KB per chunk)
    const char* aHiB = (const char*)(Ahi + ablk0 * 8192);
    const char* aLoB = (const char*)(Alo + ablk0 * 8192);
    const char* bHiB = (const char*)(Bhi + bblk0 * 8192);
    const char* bLoB = (const char*)(Blo + bblk0 * 8192);

    if (wid == 0) TCGEN05_ALLOC_CG2(sb + SM_TMEMPTR, 256);
    if (tid == 0) {
#pragma unroll
        for (int b = 0; b < NSTAGES; b++) {
            MBARRIER_INIT(sb + SM_READY(b), 8);   // 4 producer warps x 2 CTAs
            MBARRIER_INIT(sb + SM_DONE(b), 1);    // multicast commit per chunk
        }
        MBARRIER_INIT(sb + SM_FINAL, 1);          // completes EXACTLY once
    }
    __syncthreads();
    uint32_t tmem;
    asm volatile("ld.shared.b32 %0, [%1];" : "=r"(tmem) : "r"(sb + SM_TMEMPTR));

    CLUSTER_ARRIVE(); CLUSTER_WAIT();

    if (wid < 4) {
        // ============ producer warps 0-3 (both ranks), sub-tile = wid ========
        // Each warp loads its own 16KB sub-tile per chunk: 32 LDGSTS/lane,
        // commit per chunk, 2-chunk lookahead via wait_group(2).
        // DONE waits are sequential-from-phase-0 per buffer -> no aliasing.
        const char* gsrc = (wid == 0) ? aHiB : (wid == 1) ? aLoB
                         : (wid == 2) ? bHiB : bLoB;
        const uint32_t dsub = (uint32_t)wid * 16384u;
#pragma unroll 1
        for (int c = 0; c < nch; c++) {
            const int buf = c % NSTAGES;
            if (c >= NSTAGES) {
                MBARRIER_WAIT_PARITY(sb + SM_DONE(buf), ((c / NSTAGES) - 1) & 1);
            }
            const uint32_t ds = sb + SM_BUF + buf * STAGE_BYTES + dsub;
            const char* gs = gsrc + (size_t)c * 16384;
#pragma unroll
            for (int it = 0; it < 32; it++) {
                const uint32_t o = (uint32_t)(it * 32 + lid) * 16;
                CP_ASYNC16(ds + o, gs + o);
            }
            CP_COMMIT();
            if (c >= 2) {
                CP_WAITG(2);                 // this warp's chunk c-2 complete
                __syncwarp();
                FENCE_PROXY_ASYNC();
                if (elect_one())
                    MBARRIER_ARRIVE_CLUSTER(sb + SM_READY((c - 2) % NSTAGES), 0);
            }
        }
        // drain last two chunks
        CP_WAITG(1);
        __syncwarp();
        FENCE_PROXY_ASYNC();
        if (elect_one()) MBARRIER_ARRIVE_CLUSTER(sb + SM_READY((nch - 2) % NSTAGES), 0);
        CP_WAITG(0);
        __syncwarp();
        FENCE_PROXY_ASYNC();
        if (elect_one()) MBARRIER_ARRIVE_CLUSTER(sb + SM_READY((nch - 1) % NSTAGES), 0);
    } else if (wid == 4 && rank == 0 && elect_one()) {
        // ================= MMA issuer (rank 0, warp 4) =================
        // READY waits are sequential-from-phase-0 -> no aliasing.
#pragma unroll 1
        for (int c = 0; c < nch; c++) {
            const int buf = c % NSTAGES;
            MBARRIER_WAIT_PARITY(sb + SM_READY(buf), (c / NSTAGES) & 1);
            const uint32_t stage = sb + SM_BUF + buf * STAGE_BYTES;
            const uint64_t dAh = make_desc(stage + 0);
            const uint64_t dAl = make_desc(stage + 16384);
            const uint64_t dBh = make_desc(stage + 32768);
            const uint64_t dBl = make_desc(stage + 49152);
            const bool first = (c == 0);
#pragma unroll
            for (int s = 0; s < 4; s++)
                mma_f16_ss_cg2(tmem, dAh + s * 2, dBh + s * 2, MMA_IDESC_CG2, !(first && s == 0));
#pragma unroll
            for (int s = 0; s < 4; s++)
                mma_f16_ss_cg2(tmem, dAh + s * 2, dBl + s * 2, MMA_IDESC_CG2, true);
#pragma unroll
            for (int s = 0; s < 4; s++)
                mma_f16_ss_cg2(tmem, dAl + s * 2, dBh + s * 2, MMA_IDESC_CG2, true);
            TCGEN05_COMMIT_MC_CG2(sb + SM_DONE(buf));
        }
        // once-only terminal commit: FINAL goes phase 0 -> 1 exactly once, so
        // the cold parity-0 wait below is unambiguous for every thread.
        TCGEN05_COMMIT_MC_CG2(sb + SM_FINAL);
    }

    // ---------------- all threads: once-only final gate, then epilogue ------
    MBARRIER_WAIT_PARITY(sb + SM_FINAL, 0);
    TCGEN05_FENCE_AFTER();

    {
        const int sub = wid & 3, half = wid >> 2;
        const int row = sub * 32 + lid;
        float* crow = C + (size_t)blockIdx.z * M * N
                      + (size_t)(m0 + rank * 128 + row) * N + n0 + half * 128;
#pragma unroll
        for (int g = 0; g < 4; g++) {
            uint32_t regs[32];
            TCGEN05_LD_32X32B_X32(regs, tmem + half * 128 + g * 32);
            TCGEN05_WAIT_LD();
#pragma unroll
            for (int q = 0; q < 8; q++) {
                float4 f;
                f.x = __uint_as_float(regs[q * 4 + 0]);
                f.y = __uint_as_float(regs[q * 4 + 1]);
                f.z = __uint_as_float(regs[q * 4 + 2]);
                f.w = __uint_as_float(regs[q * 4 + 3]);
                *(float4*)(crow + g * 32 + q * 4) = f;
            }
        }
    }
    TCGEN05_FENCE_BEFORE();
    __syncthreads();
    if (wid == 0) {
        TCGEN05_RELINQUISH_CG2();
        TCGEN05_DEALLOC_CG2(tmem, 256);
    }
    CLUSTER_ARRIVE(); CLUSTER_WAIT();
#else
    // =============== non-feature fallback: naive tiled GEMM ===============
    // Never selected on GB300 (feature cubin exists; R6 ncu proved tensor pipe
    // active). Correct-but-slow insurance.
    const int tid = threadIdx.x;
    const int rank = (int)(blockIdx.x & 1);
    const int m0 = (int)blockIdx.y * 256 + rank * 128;
    const int n0 = (int)(blockIdx.x >> 1) * 256;
    const int mt128 = M >> 7, nt128 = N >> 7;
    const int nch = Ktot >> 6;

    auto ld2 = [&](const __nv_bfloat16* hi, const __nv_bfloat16* lo,
                   size_t tblk, int r, int e) -> float {
        const size_t blk = tblk * nch + (e >> 6);
        const uint32_t off = sw128((uint32_t)((r & 127) * 128 + (e & 63) * 2));
        float h = __bfloat162float(*(const __nv_bfloat16*)((const char*)hi + blk * 16384 + off));
        float l = __bfloat162float(*(const __nv_bfloat16*)((const char*)lo + blk * 16384 + off));
        return h + l;
    };

    const size_t atblk = (size_t)blockIdx.z * mt128 + (m0 >> 7);
    for (int idx = tid; idx < 128 * 256; idx += 256) {
        const int r = idx >> 8;
        const int j = idx & 255;
        const int gcol = n0 + j;
        const size_t btblk = (size_t)blockIdx.z * nt128 + (gcol >> 7);
        float acc = 0.0f;
        for (int e = 0; e < Ktot; e++)
            acc += ld2(Ahi, Alo, atblk, r, e) * ld2(Bhi, Blo, btblk, gcol & 127, e);
        C[(size_t)blockIdx.z * M * N + (size_t)(m0 + r) * N + gcol] = acc;
    }
#endif
}

// ---------------------------------------------------------------------------
// Q convert: fp32 row-major -> tiled SW128 bf16 hi/lo blocks.
// ---------------------------------------------------------------------------
__global__ void __launch_bounds__(256)
convert_q_kernel(const float* __restrict__ in,
                 __nv_bfloat16* __restrict__ hi, __nv_bfloat16* __restrict__ lo)
{
    const size_t i = (size_t)blockIdx.x * 256 + threadIdx.x;
    const size_t e0 = i * 8;
    const int b = (int)(e0 >> 21);              // TQ*HD = 2^21
    const int rem = (int)(e0 & ((1u << 21) - 1));
    const int q = rem >> 10;                     // HD = 1024
    const int d = rem & 1023;

    float4 v0 = *(const float4*)(in + e0);
    float4 v1 = *(const float4*)(in + e0 + 4);
    float v[8] = { v0.x, v0.y, v0.z, v0.w, v1.x, v1.y, v1.z, v1.w };
    __nv_bfloat16 h[8], l[8];
#pragma unroll
    for (int j = 0; j < 8; j++) split_bf16(v[j], h[j], l[j]);

    const size_t blk = ((size_t)b * 16 + (q >> 7)) * 16 + (d >> 6);
    const uint32_t off = sw128((uint32_t)((q & 127) * 128 + ((d & 63) >> 3) * 16));
    uint4 hv = { pack2(h[0], h[1]), pack2(h[2], h[3]), pack2(h[4], h[5]), pack2(h[6], h[7]) };
    uint4 lv = { pack2(l[0], l[1]), pack2(l[2], l[3]), pack2(l[4], l[5]), pack2(l[6], l[7]) };
    *(uint4*)((char*)hi + blk * 16384 + off) = hv;
    *(uint4*)((char*)lo + blk * 16384 + off) = lv;
}

// ---------------------------------------------------------------------------
// K convert: one read of K -> tiled K hi/lo (rows=t) AND tiled KT hi/lo (rows=d)
// ---------------------------------------------------------------------------
__global__ void __launch_bounds__(256)
k_convert_kernel(const float* __restrict__ Kin,
                 __nv_bfloat16* __restrict__ Khi, __nv_bfloat16* __restrict__ Klo,
                 __nv_bfloat16* __restrict__ KThi, __nv_bfloat16* __restrict__ KTlo)
{
    __shared__ float tile[32][33];
    const int b = blockIdx.z;
    const int t0 = blockIdx.x * 32, d0 = blockIdx.y * 32;
    const int tx = threadIdx.x & 31, ty = threadIdx.x >> 5;
    const float* src = Kin + (size_t)b * TK * HD;

#pragma unroll
    for (int r = 0; r < 4; r++) {
        const int t = t0 + ty + 8 * r;
        const int d = d0 + tx;
        const float v = src[(size_t)t * HD + d];
        tile[ty + 8 * r][tx] = v;
        __nv_bfloat16 h, l; split_bf16(v, h, l);
        const size_t blk = ((size_t)b * 16 + (t >> 7)) * 16 + (d >> 6);
        const uint32_t off = sw128((uint32_t)((t & 127) * 128 + (d & 63) * 2));
        *(__nv_bfloat16*)((char*)Khi + blk * 16384 + off) = h;
        *(__nv_bfloat16*)((char*)Klo + blk * 16384 + off) = l;
    }
    __syncthreads();
#pragma unroll
    for (int r = 0; r < 4; r++) {
        const int d = d0 + ty + 8 * r;
        const int t = t0 + tx;
        const float v = tile[tx][ty + 8 * r];
        __nv_bfloat16 h, l; split_bf16(v, h, l);
        const size_t blk = ((size_t)b * 8 + (d >> 7)) * 32 + (t >> 6);
        const uint32_t off = sw128((uint32_t)((d & 127) * 128 + (t & 63) * 2));
        *(__nv_bfloat16*)((char*)KThi + blk * 16384 + off) = h;
        *(__nv_bfloat16*)((char*)KTlo + blk * 16384 + off) = l;
    }
}

// ---------------------------------------------------------------------------
// Row softmax over TK; fp32 in (row-major), bf16 hi/lo out (TILED blocks).
// ---------------------------------------------------------------------------
__global__ void __launch_bounds__(256)
softmax_kernel(const float* __restrict__ E,
               __nv_bfloat16* __restrict__ Phi, __nv_bfloat16* __restrict__ Plo)
{
    const size_t row = blockIdx.x;
    const float* e = E + row * (size_t)TK;
    const int tid = threadIdx.x;
    const int lane = tid & 31, warp = tid >> 5;
    __shared__ float red[32];

    float4 a = *(const float4*)(e + tid * 8);
    float4 c = *(const float4*)(e + tid * 8 + 4);
    float v[8] = { a.x, a.y, a.z, a.w, c.x, c.y, c.z, c.w };

    float m = -INFINITY;
#pragma unroll
    for (int i = 0; i < 8; i++) m = fmaxf(m, v[i]);
#pragma unroll
    for (int o = 16; o > 0; o >>= 1) m = fmaxf(m, __shfl_xor_sync(0xffffffffu, m, o));
    if (lane == 0) red[warp] = m;
    __syncthreads();
    if (warp == 0) {
        float t = red[lane & 7];
#pragma unroll
        for (int o = 4; o > 0; o >>= 1) t = fmaxf(t, __shfl_xor_sync(0xffffffffu, t, o));
        red[lane] = t;
    }
    __syncthreads();
    m = red[0];

    float s = 0.0f;
#pragma unroll
    for (int i = 0; i < 8; i++) { v[i] = __expf(v[i] - m); s += v[i]; }
#pragma unroll
    for (int o = 16; o > 0; o >>= 1) s += __shfl_xor_sync(0xffffffffu, s, o);
    __syncthreads();
    if (lane == 0) red[warp] = s;
    __syncthreads();
    if (warp == 0) {
        float t = red[lane & 7];
#pragma unroll
        for (int o = 4; o > 0; o >>= 1) t += __shfl_xor_sync(0xffffffffu, t, o);
        red[lane] = t;
    }
    __syncthreads();
    const float inv = 1.0f / red[0];

    __nv_bfloat16 h[8], l[8];
#pragma unroll
    for (int i = 0; i < 8; i++) split_bf16(v[i] * inv, h[i], l[i]);

    const int b = (int)(row >> 11);             // TQ = 2048
    const int q = (int)(row & 2047);
    const size_t blk = ((size_t)b * 16 + (q >> 7)) * 32 + (tid >> 3);   // nch=32
    const uint32_t off = sw128((uint32_t)((q & 127) * 128 + (tid & 7) * 16));
    uint4 hv = { pack2(h[0], h[1]), pack2(h[2], h[3]), pack2(h[4], h[5]), pack2(h[6], h[7]) };
    uint4 lv = { pack2(l[0], l[1]), pack2(l[2], l[3]), pack2(l[4], l[5]), pack2(l[6], l[7]) };
    *(uint4*)((char*)Phi + blk * 16384 + off) = hv;
    *(uint4*)((char*)Plo + blk * 16384 + off) = lv;
}

// ---------------------------------------------------------------------------
extern "C" void kernel_launch(void* const* d_in, const int* in_sizes, int n_in,
                              void* d_out, int out_size)
{
    const float* Q  = (const float*)d_in[0];
    const float* Kt = (const float*)d_in[1];
    float* O = (float*)d_out;

    float *E; __nv_bfloat16 *Qhi, *Qlo, *Khi, *Klo, *KThi, *KTlo, *Phi, *Plo;
    cudaGetSymbolAddress((void**)&E,    g_E);
    cudaGetSymbolAddress((void**)&Qhi,  g_Qhi);
    cudaGetSymbolAddress((void**)&Qlo,  g_Qlo);
    cudaGetSymbolAddress((void**)&Khi,  g_Khi);
    cudaGetSymbolAddress((void**)&Klo,  g_Klo);
    cudaGetSymbolAddress((void**)&KThi, g_KThi);
    cudaGetSymbolAddress((void**)&KTlo, g_KTlo);
    cudaGetSymbolAddress((void**)&Phi,  g_Phi);
    cudaGetSymbolAddress((void**)&Plo,  g_Plo);

    cudaFuncSetAttribute(gemm_split_kernel,
                         cudaFuncAttributeMaxDynamicSharedMemorySize, GEMM_SMEM);

    // Q -> tiled hi/lo
    {
        size_t n8 = (size_t)BATCH * TQ * HD / 8;
        convert_q_kernel<<<(unsigned)(n8 / 256), 256>>>(Q, Qhi, Qlo);
    }
    // K -> tiled K hi/lo + tiled KT hi/lo
    {
        dim3 grid(TK / 32, HD / 32, BATCH);
        k_convert_kernel<<<grid, 256>>>(Kt, Khi, Klo, KThi, KTlo);
    }
    // GEMM1: E = Q K^T  (M=TQ, N=TK, Ktot=HD)
    {
        dim3 grid((TK / 256) * 2, TQ / 256, BATCH);
        gemm_split_kernel<<<grid, 256, GEMM_SMEM>>>(Qhi, Qlo, Khi, Klo, E, TQ, TK, HD);
    }
    softmax_kernel<<<BATCH * TQ, 256>>>(E, Phi, Plo);
    // GEMM2: O = P KT^T  (M=TQ, N=HD, Ktot=TK)
    {
        dim3 grid((HD / 256) * 2, TQ / 256, BATCH);
        gemm_split_kernel<<<grid, 256, GEMM_SMEM>>>(Phi, Plo, KThi, KTlo, O, TQ, HD, TK);
    }
    (void)in_sizes; (void)n_in; (void)out_size;
}

// round 14
// speedup vs baseline: 1.2364x; 1.1327x over previous
#include <cuda_runtime.h>
#include <cuda_bf16.h>
#include <cstdint>
#include <math.h>

#define BATCH 8
#define TQ    2048
#define TK    2048
#define HD    1024

#if defined(__CUDA_ARCH_FEAT_SM103_ALL) || defined(__CUDA_ARCH_FEAT_SM100_ALL)
#define HAS_TCGEN05 1
#else
#define HAS_TCGEN05 0
#endif

// ---------------------------------------------------------------------------
// Device scratch. GEMM operands stored TILED: contiguous 16KB blocks that are
// the exact SW128 smem image of a 128-row x 64-col bf16 sub-tile.
//   Q  : [B][TQ/128=16][HD/64=16] blocks
//   K  : [B][TK/128=16][HD/64=16] blocks
//   KT : [B][HD/128= 8][TK/64=32] blocks
//   P  : [B][TQ/128=16][TK/64=32] blocks
// ---------------------------------------------------------------------------
__device__ float         g_E   [(size_t)BATCH * TQ * TK];
__device__ __nv_bfloat16 g_Qhi [(size_t)BATCH * TQ * HD];
__device__ __nv_bfloat16 g_Qlo [(size_t)BATCH * TQ * HD];
__device__ __nv_bfloat16 g_Khi [(size_t)BATCH * TK * HD];
__device__ __nv_bfloat16 g_Klo [(size_t)BATCH * TK * HD];
__device__ __nv_bfloat16 g_KThi[(size_t)BATCH * HD * TK];
__device__ __nv_bfloat16 g_KTlo[(size_t)BATCH * HD * TK];
__device__ __nv_bfloat16 g_Phi [(size_t)BATCH * TQ * TK];
__device__ __nv_bfloat16 g_Plo [(size_t)BATCH * TQ * TK];

// ---------------------------------------------------------------------------
// Common helpers
// ---------------------------------------------------------------------------
__device__ __forceinline__ uint32_t smem_u32(const void* p) {
    uint32_t a;
    asm("{ .reg .u64 t; cvta.to.shared.u64 t, %1; cvt.u32.u64 %0, t; }" : "=r"(a) : "l"(p));
    return a;
}

__device__ __forceinline__ void split_bf16(float x, __nv_bfloat16& h, __nv_bfloat16& l) {
    h = __float2bfloat16(x);
    l = __float2bfloat16(x - __bfloat162float(h));
}

__device__ __forceinline__ uint32_t pack2(__nv_bfloat16 a, __nv_bfloat16 b) {
    __nv_bfloat162 t(a, b);
    return *(uint32_t*)&t;
}

__device__ __forceinline__ uint32_t sw128(uint32_t off) {
    return off ^ ((off >> 3) & 0x70);
}

#define CP_ASYNC16(dst, src) \
    asm volatile("cp.async.cg.shared.global [%0], [%1], 16;" :: "r"(dst), "l"(src) : "memory")
#define CP_COMMIT()  asm volatile("cp.async.commit_group;" ::: "memory")
#define CP_WAITG(n)  asm volatile("cp.async.wait_group %0;" :: "n"(n) : "memory")

#define CLUSTER_ARRIVE() asm volatile("barrier.cluster.arrive.aligned;" ::: "memory")
#define CLUSTER_WAIT()   asm volatile("barrier.cluster.wait.aligned;"   ::: "memory")

// ---------------------------------------------------------------------------
// tcgen05 helpers (only in the sm_103a feature pass)
// ---------------------------------------------------------------------------
#if HAS_TCGEN05
#define MBARRIER_INIT(addr, cnt) \
    asm volatile("mbarrier.init.shared.b64 [%0], %1;" :: "r"((uint32_t)(addr)), "r"((uint32_t)(cnt)) : "memory")

#define MBARRIER_WAIT_PARITY(addr, parity) do {                                              \
    uint32_t _m = (uint32_t)(addr); uint32_t _p = (uint32_t)(parity); uint32_t _d;            \
    asm volatile("{\n\t.reg .pred p;\n\t"                                                     \
        "mbarrier.try_wait.parity.acquire.cta.shared::cta.b64 p, [%1], %2;\n\t"               \
        "selp.b32 %0, 1, 0, p;\n\t}" : "=r"(_d) : "r"(_m), "r"(_p) : "memory");               \
    if (!_d) {                                                                                \
        asm volatile("{\n\t.reg .pred P1;\n\t"                                                \
            "WL_%=:\n\t"                                                                      \
            "mbarrier.try_wait.parity.acquire.cta.shared::cta.b64 P1, [%0], %1, 0x989680;\n\t"\
            "@P1 bra.uni WD_%=;\n\t"                                                          \
            "bra.uni WL_%=;\n\t"                                                              \
            "WD_%=:\n\t}" :: "r"(_m), "r"(_p) : "memory");                                    \
    }                                                                                         \
} while (0)

// arrive on the same-offset mbarrier in cluster CTA `rank` (R8-proven)
#define MBARRIER_ARRIVE_CLUSTER(local_addr, rank) \
    asm volatile("{\n\t.reg .b32 r;\n\t" \
        "mapa.shared::cluster.u32 r, %0, %1;\n\t" \
        "mbarrier.arrive.release.cluster.shared::cluster.b64 _, [r];\n\t}" \
        :: "r"((uint32_t)(local_addr)), "r"((uint32_t)(rank)) : "memory")

#define TCGEN05_ALLOC_CG2(smem_addr, ncols) \
    asm volatile("tcgen05.alloc.cta_group::2.sync.aligned.shared::cta.b32 [%0], %1;" \
                 :: "r"((uint32_t)(smem_addr)), "r"((uint32_t)(ncols)) : "memory")
#define TCGEN05_DEALLOC_CG2(tmem, ncols) \
    asm volatile("tcgen05.dealloc.cta_group::2.sync.aligned.b32 %0, %1;" :: "r"(tmem), "r"((uint32_t)(ncols)))
#define TCGEN05_RELINQUISH_CG2() \
    asm volatile("tcgen05.relinquish_alloc_permit.cta_group::2.sync.aligned;")
#define TCGEN05_COMMIT_MC_CG2(mbar) \
    asm volatile("tcgen05.commit.cta_group::2.mbarrier::arrive::one.shared::cluster.multicast::cluster.b64 [%0], %1;" \
                 :: "r"((uint32_t)(mbar)), "h"((uint16_t)0x3) : "memory")
#define TCGEN05_FENCE_AFTER()  asm volatile("tcgen05.fence::after_thread_sync;"  ::: "memory")
#define TCGEN05_FENCE_BEFORE() asm volatile("tcgen05.fence::before_thread_sync;" ::: "memory")
#define TCGEN05_WAIT_LD()      asm volatile("tcgen05.wait::ld.sync.aligned;"     ::: "memory")
#define FENCE_PROXY_ASYNC()    asm volatile("fence.proxy.async.shared::cta;"     ::: "memory")

#define TCGEN05_LD_32X32B_X32(r, tmem_addr) \
    asm volatile( \
        "tcgen05.ld.sync.aligned.32x32b.x32.b32 " \
        "{%0, %1, %2, %3, %4, %5, %6, %7, " \
        " %8, %9, %10, %11, %12, %13, %14, %15, " \
        " %16, %17, %18, %19, %20, %21, %22, %23, " \
        " %24, %25, %26, %27, %28, %29, %30, %31}, [%32];" \
        : "=r"((r)[0]),  "=r"((r)[1]),  "=r"((r)[2]),  "=r"((r)[3]), \
          "=r"((r)[4]),  "=r"((r)[5]),  "=r"((r)[6]),  "=r"((r)[7]), \
          "=r"((r)[8]),  "=r"((r)[9]),  "=r"((r)[10]), "=r"((r)[11]), \
          "=r"((r)[12]), "=r"((r)[13]), "=r"((r)[14]), "=r"((r)[15]), \
          "=r"((r)[16]), "=r"((r)[17]), "=r"((r)[18]), "=r"((r)[19]), \
          "=r"((r)[20]), "=r"((r)[21]), "=r"((r)[22]), "=r"((r)[23]), \
          "=r"((r)[24]), "=r"((r)[25]), "=r"((r)[26]), "=r"((r)[27]), \
          "=r"((r)[28]), "=r"((r)[29]), "=r"((r)[30]), "=r"((r)[31]) \
        : "r"(tmem_addr))

__device__ __forceinline__ void mma_f16_ss_cg2(uint32_t d, uint64_t ad, uint64_t bd,
                                               uint32_t idesc, bool acc) {
    uint32_t en = acc ? 1u : 0u;
    asm volatile(
        "{\n\t.reg .pred p;\n\tsetp.ne.u32 p, %5, 0;\n\t"
        "tcgen05.mma.cta_group::2.kind::f16 [%0], %1, %2, %3, "
        "{%4, %4, %4, %4, %4, %4, %4, %4}, p;\n\t}"
        :: "r"(d), "l"(ad), "l"(bd), "r"(idesc), "r"(0u), "r"(en) : "memory");
}

__device__ __forceinline__ uint64_t make_desc(uint32_t addr) {
    const uint64_t base = (2ULL << 61) | (1ULL << 46) | (64ULL << 32) | (1ULL << 16);
    return base | ((uint64_t)(addr >> 4) & 0x3FFF);
}
// dtype=F32, a/b=BF16, N=256 (32<<17), M=256 (16<<24) for cta_group::2
#define MMA_IDESC_CG2 0x10400490u
#endif  // HAS_TCGEN05

// ---------------------------------------------------------------------------
// GEMM: C[M,N] = (Ahi+Alo)[M,Kt] * (Bhi+Blo)[N,Kt]^T, fp32 out, TILED operands.
// 2-CTA cluster tile: M=256 (128/CTA) x N=512 (two N=256 MMA halves, B split
// 128 rows per CTA per half). K chunk 64, 2 smem stages of 96KB.
// All-warps cp.async producer loop (R8-proven shape); rank0 lane0 issues
// 24 cg2 MMAs/chunk (D0 @ TMEM col 0, D1 @ col 256). FINAL barrier gates
// the epilogue (once-only, no parity aliasing).
// Grid: x = (N/512)*2, y = M/256, z = batch.
// ---------------------------------------------------------------------------
#define NSTAGES     2
#define SM_TMEMPTR  0
#define SM_READY(b) (16 + 8 * (b))
#define SM_DONE(b)  (48 + 8 * (b))
#define SM_FINAL    72
#define SM_BUF      1024
#define STAGE_BYTES 98304          // Ahi|Alo|Bhi0|Bhi1|Blo0|Blo1, 16KB each
#define GEMM_SMEM   (SM_BUF + NSTAGES * STAGE_BYTES)

__global__ void __launch_bounds__(256, 1) __cluster_dims__(2, 1, 1)
gemm_split_kernel(const __nv_bfloat16* __restrict__ Ahi, const __nv_bfloat16* __restrict__ Alo,
                  const __nv_bfloat16* __restrict__ Bhi, const __nv_bfloat16* __restrict__ Blo,
                  float* __restrict__ C, int M, int N, int Ktot)
{
#if HAS_TCGEN05
    extern __shared__ char smem[];
    const uint32_t sb = smem_u32(smem);
    const int tid = threadIdx.x;
    const int wid = tid >> 5, lid = tid & 31;
    const int rank = (int)(blockIdx.x & 1);
    const int n0 = (int)(blockIdx.x >> 1) * 512;
    const int m0 = (int)blockIdx.y * 256;

    const int mt128 = M >> 7, nt128 = N >> 7;
    const int nch = Ktot >> 6;
    const int atile = (int)blockIdx.y * 2 + rank;
    const size_t ablk0 = ((size_t)blockIdx.z * mt128 + atile) * nch;
    // B half h: this CTA holds rows n0 + h*256 + rank*128 .. +127
    const size_t bblk0h0 = ((size_t)blockIdx.z * nt128 + (n0 >> 7) + 0 + rank) * nch;
    const size_t bblk0h1 = ((size_t)blockIdx.z * nt128 + (n0 >> 7) + 2 + rank) * nch;

    // 6 sub-block sources, each a run of nch contiguous 16KB blocks
    const char* srcs[6] = {
        (const char*)(Ahi + ablk0 * 8192),
        (const char*)(Alo + ablk0 * 8192),
        (const char*)(Bhi + bblk0h0 * 8192),
        (const char*)(Bhi + bblk0h1 * 8192),
        (const char*)(Blo + bblk0h0 * 8192),
        (const char*)(Blo + bblk0h1 * 8192),
    };

    if (wid == 0) TCGEN05_ALLOC_CG2(sb + SM_TMEMPTR, 512);
    if (tid == 0) {
#pragma unroll
        for (int b = 0; b < NSTAGES; b++) {
            MBARRIER_INIT(sb + SM_READY(b), 2);   // tid0 of each CTA
            MBARRIER_INIT(sb + SM_DONE(b), 1);    // multicast commit per chunk
        }
        MBARRIER_INIT(sb + SM_FINAL, 1);          // completes EXACTLY once
    }
    __syncthreads();
    uint32_t tmem;
    asm volatile("ld.shared.b32 %0, [%1];" : "=r"(tmem) : "r"(sb + SM_TMEMPTR));

    CLUSTER_ARRIVE(); CLUSTER_WAIT();

    // issue one chunk's 96KB into stage buffer: 24 cp.async per thread
    auto issue_chunk = [&](int c, int buf) {
        const uint32_t stage = sb + SM_BUF + buf * STAGE_BYTES;
        const size_t coff = (size_t)c * 16384;
#pragma unroll
        for (int s = 0; s < 6; s++) {
            const char* gs = srcs[s] + coff;
            const uint32_t ds = stage + s * 16384;
#pragma unroll
            for (int j = 0; j < 4; j++) {
                const uint32_t o = (uint32_t)(tid + j * 256) * 16;
                CP_ASYNC16(ds + o, gs + o);
            }
        }
        CP_COMMIT();
    };

    // prologue: chunks 0 and 1
    issue_chunk(0, 0);
    if (nch > 1) issue_chunk(1, 1);

#pragma unroll 1
    for (int c = 0; c < nch; c++) {
        const int buf = c & 1;
        if (c + 1 < nch) { CP_WAITG(1); } else { CP_WAITG(0); }
        __syncthreads();
        FENCE_PROXY_ASYNC();
        if (tid == 0) MBARRIER_ARRIVE_CLUSTER(sb + SM_READY(buf), 0);

        if (rank == 0 && tid == 0) {
            MBARRIER_WAIT_PARITY(sb + SM_READY(buf), (c >> 1) & 1);
            const uint32_t stage = sb + SM_BUF + buf * STAGE_BYTES;
            const uint64_t dAh  = make_desc(stage + 0);
            const uint64_t dAl  = make_desc(stage + 16384);
            const uint64_t dBh0 = make_desc(stage + 32768);
            const uint64_t dBh1 = make_desc(stage + 49152);
            const uint64_t dBl0 = make_desc(stage + 65536);
            const uint64_t dBl1 = make_desc(stage + 81920);
            const bool first = (c == 0);
            // half 0 -> D @ col 0
#pragma unroll
            for (int s = 0; s < 4; s++)
                mma_f16_ss_cg2(tmem, dAh + s * 2, dBh0 + s * 2, MMA_IDESC_CG2, !(first && s == 0));
#pragma unroll
            for (int s = 0; s < 4; s++)
                mma_f16_ss_cg2(tmem, dAh + s * 2, dBl0 + s * 2, MMA_IDESC_CG2, true);
#pragma unroll
            for (int s = 0; s < 4; s++)
                mma_f16_ss_cg2(tmem, dAl + s * 2, dBh0 + s * 2, MMA_IDESC_CG2, true);
            // half 1 -> D @ col 256
#pragma unroll
            for (int s = 0; s < 4; s++)
                mma_f16_ss_cg2(tmem + 256, dAh + s * 2, dBh1 + s * 2, MMA_IDESC_CG2, !(first && s == 0));
#pragma unroll
            for (int s = 0; s < 4; s++)
                mma_f16_ss_cg2(tmem + 256, dAh + s * 2, dBl1 + s * 2, MMA_IDESC_CG2, true);
#pragma unroll
            for (int s = 0; s < 4; s++)
                mma_f16_ss_cg2(tmem + 256, dAl + s * 2, dBh1 + s * 2, MMA_IDESC_CG2, true);
            TCGEN05_COMMIT_MC_CG2(sb + SM_DONE(buf));
        }

        // all threads: reuse this buffer for chunk c+2 once chunk c's MMAs done
        if (c + 2 < nch) {
            MBARRIER_WAIT_PARITY(sb + SM_DONE(buf), (c >> 1) & 1);
            issue_chunk(c + 2, buf);
        }
    }

    // once-only terminal commit (same thread that issued all MMAs)
    if (rank == 0 && tid == 0) TCGEN05_COMMIT_MC_CG2(sb + SM_FINAL);

    // ---------------- all threads: once-only final gate, then epilogue ------
    MBARRIER_WAIT_PARITY(sb + SM_FINAL, 0);
    TCGEN05_FENCE_AFTER();

    {
        const int sub = wid & 3, half = wid >> 2;     // 8 warps: 4 row-groups x 2 col-halves
        const int row = sub * 32 + lid;
        float* crow = C + (size_t)blockIdx.z * M * N
                      + (size_t)(m0 + rank * 128 + row) * N + n0 + half * 256;
#pragma unroll
        for (int g = 0; g < 8; g++) {
            uint32_t regs[32];
            TCGEN05_LD_32X32B_X32(regs, tmem + half * 256 + g * 32);
            TCGEN05_WAIT_LD();
#pragma unroll
            for (int q = 0; q < 8; q++) {
                float4 f;
                f.x = __uint_as_float(regs[q * 4 + 0]);
                f.y = __uint_as_float(regs[q * 4 + 1]);
                f.z = __uint_as_float(regs[q * 4 + 2]);
                f.w = __uint_as_float(regs[q * 4 + 3]);
                *(float4*)(crow + g * 32 + q * 4) = f;
            }
        }
    }
    TCGEN05_FENCE_BEFORE();
    __syncthreads();
    if (wid == 0) {
        TCGEN05_RELINQUISH_CG2();
        TCGEN05_DEALLOC_CG2(tmem, 512);
    }
    CLUSTER_ARRIVE(); CLUSTER_WAIT();
#else
    // =============== non-feature fallback: naive tiled GEMM ===============
    // Never selected on GB300 (feature cubin exists; ncu shows tensor pipe
    // active). Correct-but-slow insurance.
    const int tid = threadIdx.x;
    const int rank = (int)(blockIdx.x & 1);
    const int m0 = (int)blockIdx.y * 256 + rank * 128;
    const int n0 = (int)(blockIdx.x >> 1) * 512;
    const int mt128 = M >> 7, nt128 = N >> 7;
    const int nch = Ktot >> 6;

    auto ld2 = [&](const __nv_bfloat16* hi, const __nv_bfloat16* lo,
                   size_t tblk, int r, int e) -> float {
        const size_t blk = tblk * nch + (e >> 6);
        const uint32_t off = sw128((uint32_t)((r & 127) * 128 + (e & 63) * 2));
        float h = __bfloat162float(*(const __nv_bfloat16*)((const char*)hi + blk * 16384 + off));
        float l = __bfloat162float(*(const __nv_bfloat16*)((const char*)lo + blk * 16384 + off));
        return h + l;
    };

    const size_t atblk = (size_t)blockIdx.z * mt128 + (m0 >> 7);
    for (int idx = tid; idx < 128 * 512; idx += 256) {
        const int r = idx >> 9;
        const int j = idx & 511;
        const int gcol = n0 + j;
        const size_t btblk = (size_t)blockIdx.z * nt128 + (gcol >> 7);
        float acc = 0.0f;
        for (int e = 0; e < Ktot; e++)
            acc += ld2(Ahi, Alo, atblk, r, e) * ld2(Bhi, Blo, btblk, gcol & 127, e);
        C[(size_t)blockIdx.z * M * N + (size_t)(m0 + r) * N + gcol] = acc;
    }
#endif
}

// ---------------------------------------------------------------------------
// Q convert: fp32 row-major -> tiled SW128 bf16 hi/lo blocks.
// ---------------------------------------------------------------------------
__global__ void __launch_bounds__(256)
convert_q_kernel(const float* __restrict__ in,
                 __nv_bfloat16* __restrict__ hi, __nv_bfloat16* __restrict__ lo)
{
    const size_t i = (size_t)blockIdx.x * 256 + threadIdx.x;
    const size_t e0 = i * 8;
    const int b = (int)(e0 >> 21);              // TQ*HD = 2^21
    const int rem = (int)(e0 & ((1u << 21) - 1));
    const int q = rem >> 10;                     // HD = 1024
    const int d = rem & 1023;

    float4 v0 = *(const float4*)(in + e0);
    float4 v1 = *(const float4*)(in + e0 + 4);
    float v[8] = { v0.x, v0.y, v0.z, v0.w, v1.x, v1.y, v1.z, v1.w };
    __nv_bfloat16 h[8], l[8];
#pragma unroll
    for (int j = 0; j < 8; j++) split_bf16(v[j], h[j], l[j]);

    const size_t blk = ((size_t)b * 16 + (q >> 7)) * 16 + (d >> 6);
    const uint32_t off = sw128((uint32_t)((q & 127) * 128 + ((d & 63) >> 3) * 16));
    uint4 hv = { pack2(h[0], h[1]), pack2(h[2], h[3]), pack2(h[4], h[5]), pack2(h[6], h[7]) };
    uint4 lv = { pack2(l[0], l[1]), pack2(l[2], l[3]), pack2(l[4], l[5]), pack2(l[6], l[7]) };
    *(uint4*)((char*)hi + blk * 16384 + off) = hv;
    *(uint4*)((char*)lo + blk * 16384 + off) = lv;
}

// ---------------------------------------------------------------------------
// K convert: one read of K -> tiled K hi/lo (rows=t) AND tiled KT hi/lo (rows=d)
// ---------------------------------------------------------------------------
__global__ void __launch_bounds__(256)
k_convert_kernel(const float* __restrict__ Kin,
                 __nv_bfloat16* __restrict__ Khi, __nv_bfloat16* __restrict__ Klo,
                 __nv_bfloat16* __restrict__ KThi, __nv_bfloat16* __restrict__ KTlo)
{
    __shared__ float tile[32][33];
    const int b = blockIdx.z;
    const int t0 = blockIdx.x * 32, d0 = blockIdx.y * 32;
    const int tx = threadIdx.x & 31, ty = threadIdx.x >> 5;
    const float* src = Kin + (size_t)b * TK * HD;

#pragma unroll
    for (int r = 0; r < 4; r++) {
        const int t = t0 + ty + 8 * r;
        const int d = d0 + tx;
        const float v = src[(size_t)t * HD + d];
        tile[ty + 8 * r][tx] = v;
        __nv_bfloat16 h, l; split_bf16(v, h, l);
        const size_t blk = ((size_t)b * 16 + (t >> 7)) * 16 + (d >> 6);
        const uint32_t off = sw128((uint32_t)((t & 127) * 128 + (d & 63) * 2));
        *(__nv_bfloat16*)((char*)Khi + blk * 16384 + off) = h;
        *(__nv_bfloat16*)((char*)Klo + blk * 16384 + off) = l;
    }
    __syncthreads();
#pragma unroll
    for (int r = 0; r < 4; r++) {
        const int d = d0 + ty + 8 * r;
        const int t = t0 + tx;
        const float v = tile[tx][ty + 8 * r];
        __nv_bfloat16 h, l; split_bf16(v, h, l);
        const size_t blk = ((size_t)b * 8 + (d >> 7)) * 32 + (t >> 6);
        const uint32_t off = sw128((uint32_t)((d & 127) * 128 + (t & 63) * 2));
        *(__nv_bfloat16*)((char*)KThi + blk * 16384 + off) = h;
        *(__nv_bfloat16*)((char*)KTlo + blk * 16384 + off) = l;
    }
}

// ---------------------------------------------------------------------------
// Row softmax over TK; fp32 in (row-major), bf16 hi/lo out (TILED blocks).
// ---------------------------------------------------------------------------
__global__ void __launch_bounds__(256)
softmax_kernel(const float* __restrict__ E,
               __nv_bfloat16* __restrict__ Phi, __nv_bfloat16* __restrict__ Plo)
{
    const size_t row = blockIdx.x;
    const float* e = E + row * (size_t)TK;
    const int tid = threadIdx.x;
    const int lane = tid & 31, warp = tid >> 5;
    __shared__ float red[32];

    float4 a = *(const float4*)(e + tid * 8);
    float4 c = *(const float4*)(e + tid * 8 + 4);
    float v[8] = { a.x, a.y, a.z, a.w, c.x, c.y, c.z, c.w };

    float m = -INFINITY;
#pragma unroll
    for (int i = 0; i < 8; i++) m = fmaxf(m, v[i]);
#pragma unroll
    for (int o = 16; o > 0; o >>= 1) m = fmaxf(m, __shfl_xor_sync(0xffffffffu, m, o));
    if (lane == 0) red[warp] = m;
    __syncthreads();
    if (warp == 0) {
        float t = red[lane & 7];
#pragma unroll
        for (int o = 4; o > 0; o >>= 1) t = fmaxf(t, __shfl_xor_sync(0xffffffffu, t, o));
        red[lane] = t;
    }
    __syncthreads();
    m = red[0];

    float s = 0.0f;
#pragma unroll
    for (int i = 0; i < 8; i++) { v[i] = __expf(v[i] - m); s += v[i]; }
#pragma unroll
    for (int o = 16; o > 0; o >>= 1) s += __shfl_xor_sync(0xffffffffu, s, o);
    __syncthreads();
    if (lane == 0) red[warp] = s;
    __syncthreads();
    if (warp == 0) {
        float t = red[lane & 7];
#pragma unroll
        for (int o = 4; o > 0; o >>= 1) t += __shfl_xor_sync(0xffffffffu, t, o);
        red[lane] = t;
    }
    __syncthreads();
    const float inv = 1.0f / red[0];

    __nv_bfloat16 h[8], l[8];
#pragma unroll
    for (int i = 0; i < 8; i++) split_bf16(v[i] * inv, h[i], l[i]);

    const int b = (int)(row >> 11);             // TQ = 2048
    const int q = (int)(row & 2047);
    const size_t blk = ((size_t)b * 16 + (q >> 7)) * 32 + (tid >> 3);   // nch=32
    const uint32_t off = sw128((uint32_t)((q & 127) * 128 + (tid & 7) * 16));
    uint4 hv = { pack2(h[0], h[1]), pack2(h[2], h[3]), pack2(h[4], h[5]), pack2(h[6], h[7]) };
    uint4 lv = { pack2(l[0], l[1]), pack2(l[2], l[3]), pack2(l[4], l[5]), pack2(l[6], l[7]) };
    *(uint4*)((char*)Phi + blk * 16384 + off) = hv;
    *(uint4*)((char*)Plo + blk * 16384 + off) = lv;
}

// ---------------------------------------------------------------------------
extern "C" void kernel_launch(void* const* d_in, const int* in_sizes, int n_in,
                              void* d_out, int out_size)
{
    const float* Q  = (const float*)d_in[0];
    const float* Kt = (const float*)d_in[1];
    float* O = (float*)d_out;

    float *E; __nv_bfloat16 *Qhi, *Qlo, *Khi, *Klo, *KThi, *KTlo, *Phi, *Plo;
    cudaGetSymbolAddress((void**)&E,    g_E);
    cudaGetSymbolAddress((void**)&Qhi,  g_Qhi);
    cudaGetSymbolAddress((void**)&Qlo,  g_Qlo);
    cudaGetSymbolAddress((void**)&Khi,  g_Khi);
    cudaGetSymbolAddress((void**)&Klo,  g_Klo);
    cudaGetSymbolAddress((void**)&KThi, g_KThi);
    cudaGetSymbolAddress((void**)&KTlo, g_KTlo);
    cudaGetSymbolAddress((void**)&Phi,  g_Phi);
    cudaGetSymbolAddress((void**)&Plo,  g_Plo);

    cudaFuncSetAttribute(gemm_split_kernel,
                         cudaFuncAttributeMaxDynamicSharedMemorySize, GEMM_SMEM);

    // Q -> tiled hi/lo
    {
        size_t n8 = (size_t)BATCH * TQ * HD / 8;
        convert_q_kernel<<<(unsigned)(n8 / 256), 256>>>(Q, Qhi, Qlo);
    }
    // K -> tiled K hi/lo + tiled KT hi/lo
    {
        dim3 grid(TK / 32, HD / 32, BATCH);
        k_convert_kernel<<<grid, 256>>>(Kt, Khi, Klo, KThi, KTlo);
    }
    // GEMM1: E = Q K^T  (M=TQ, N=TK, Ktot=HD)
    {
        dim3 grid((TK / 512) * 2, TQ / 256, BATCH);
        gemm_split_kernel<<<grid, 256, GEMM_SMEM>>>(Qhi, Qlo, Khi, Klo, E, TQ, TK, HD);
    }
    softmax_kernel<<<BATCH * TQ, 256>>>(E, Phi, Plo);
    // GEMM2: O = P KT^T  (M=TQ, N=HD, Ktot=TK)
    {
        dim3 grid((HD / 512) * 2, TQ / 256, BATCH);
        gemm_split_kernel<<<grid, 256, GEMM_SMEM>>>(Phi, Plo, KThi, KTlo, O, TQ, HD, TK);
    }
    (void)in_sizes; (void)n_in; (void)out_size;
}